// round 2
// baseline (speedup 1.0000x reference)
#include <cuda_runtime.h>
#include <math.h>

#define Bv    4
#define Tv    2048
#define Dv    1024
#define Hv    16
#define DHv   64
#define HALFv 32
#define MROWS (Bv*Tv)      // 8192
#define NQKV  (3*Dv)       // 3072

// ---- scratch (device globals: no allocation allowed in kernel_launch) ----
__device__ float g_q[Bv*Hv*Tv*DHv];     // [b,h,t,dh]
__device__ float g_k[Bv*Hv*Tv*DHv];
__device__ float g_v[Bv*Hv*Tv*DHv];
__device__ float g_attn[MROWS*Dv];      // [b,t,d]

// ============================================================================
// GEMM: C[M,N] = A[M,K] * Bw[N,K]^T   (K = Dv = 1024)
// 128x128x8 tile, 256 threads, 8x8 micro-tile per thread.
// MODE 0: scatter into g_q/g_k/g_v ([b,h,t,dh] layout). MODE 1: row-major C.
// ============================================================================
template<int MODE>
__global__ __launch_bounds__(256)
void gemm_tn(const float* __restrict__ A, const float* __restrict__ Bw,
             float* __restrict__ C)
{
    __shared__ float As[8][128];   // [k][m]
    __shared__ float Bs[8][128];   // [k][n]
    const int tid = threadIdx.x;
    const int tx = tid & 15, ty = tid >> 4;
    const int m0 = blockIdx.y * 128, n0 = blockIdx.x * 128;
    const int lr = tid >> 1, lk = (tid & 1) * 4;

    const float* Ap = A + (size_t)(m0 + lr) * Dv + lk;
    const float* Bp = Bw + (size_t)(n0 + lr) * Dv + lk;

    float acc[8][8];
    #pragma unroll
    for (int i = 0; i < 8; i++)
        #pragma unroll
        for (int j = 0; j < 8; j++) acc[i][j] = 0.f;

    for (int kt = 0; kt < Dv; kt += 8) {
        float4 av = *(const float4*)(Ap + kt);
        float4 bv = *(const float4*)(Bp + kt);
        __syncthreads();
        As[lk+0][lr] = av.x; As[lk+1][lr] = av.y;
        As[lk+2][lr] = av.z; As[lk+3][lr] = av.w;
        Bs[lk+0][lr] = bv.x; Bs[lk+1][lr] = bv.y;
        Bs[lk+2][lr] = bv.z; Bs[lk+3][lr] = bv.w;
        __syncthreads();
        #pragma unroll
        for (int kk = 0; kk < 8; kk++) {
            float4 a0 = *(const float4*)&As[kk][ty*8];
            float4 a1 = *(const float4*)&As[kk][ty*8+4];
            float4 b0 = *(const float4*)&Bs[kk][tx*8];
            float4 b1 = *(const float4*)&Bs[kk][tx*8+4];
            float a[8] = {a0.x,a0.y,a0.z,a0.w,a1.x,a1.y,a1.z,a1.w};
            float b[8] = {b0.x,b0.y,b0.z,b0.w,b1.x,b1.y,b1.z,b1.w};
            #pragma unroll
            for (int i = 0; i < 8; i++)
                #pragma unroll
                for (int j = 0; j < 8; j++)
                    acc[i][j] = fmaf(a[i], b[j], acc[i][j]);
        }
    }

    if (MODE == 0) {
        #pragma unroll
        for (int i = 0; i < 8; i++) {
            int m = m0 + ty*8 + i;
            int bb = m >> 11, t = m & (Tv - 1);
            #pragma unroll
            for (int j = 0; j < 8; j++) {
                int n  = n0 + tx*8 + j;
                int wh = n >> 10;          // 0=q 1=k 2=v
                int d  = n & (Dv - 1);
                int h  = d >> 6, dd = d & 63;
                float* dst = (wh == 0) ? g_q : (wh == 1) ? g_k : g_v;
                dst[((bb*Hv + h)*Tv + t)*DHv + dd] = acc[i][j];
            }
        }
    } else {
        #pragma unroll
        for (int i = 0; i < 8; i++) {
            int m = m0 + ty*8 + i;
            #pragma unroll
            for (int j = 0; j < 8; j++)
                C[(size_t)m * Dv + n0 + tx*8 + j] = acc[i][j];
        }
    }
}

// ============================================================================
// RoPE on g_q and g_k in place. One thread per (b,h,t,i<HALF) pair.
// ============================================================================
__global__ void rope_kernel(const float* __restrict__ cosT,
                            const float* __restrict__ sinT)
{
    int gid = blockIdx.x * blockDim.x + threadIdx.x;
    if (gid >= Bv*Hv*Tv*HALFv) return;
    int i   = gid & (HALFv - 1);
    int row = gid >> 5;              // bh*T + t
    int t   = row & (Tv - 1);
    float c = cosT[t*HALFv + i];
    float s = sinT[t*HALFv + i];

    float* qp = g_q + (size_t)row * DHv;
    float q1 = qp[i], q2 = qp[i + HALFv];
    qp[i]          = q1*c - q2*s;
    qp[i + HALFv]  = q1*s + q2*c;

    float* kp = g_k + (size_t)row * DHv;
    float k1 = kp[i], k2 = kp[i + HALFv];
    kp[i]          = k1*c - k2*s;
    kp[i + HALFv]  = k1*s + k2*c;
}

// ============================================================================
// Flash attention, causal, with diagonal excluded from the PV numerator
// (softmax denominator still includes the diagonal => matches
//  out = softmax(w)@v - diag(w)*v).
// Block: 64 q-rows x full head. 256 threads, 4x4 micro-tiles for both
// S = Q K^T and O = P V (each a 64x64x64 register-tiled GEMM).
// smem: Qs (Q^T, [d][q]), KPs (K^T [d][c], later P [q][c]), Vs ([c][dh]).
// ============================================================================
__global__ __launch_bounds__(256)
void attn_kernel()
{
    __shared__ float Qs[64][64];   // [d][q]
    __shared__ float KPs[64][64];  // K^T [d][c], then P [q][c]
    __shared__ float Vs[64][64];   // [c][dh]

    const int qb = blockIdx.x;     // q block (0..31)
    const int bh = blockIdx.y;     // b*H + h  (0..63)
    const int tid = threadIdx.x;
    const int tx = tid & 15, ty = tid >> 4;

    // cooperative transposed load of Q tile
    {
        int r = tid >> 2, ds = (tid & 3) << 4;
        const float* qp = g_q + ((size_t)bh*Tv + qb*64 + r)*DHv + ds;
        #pragma unroll
        for (int i = 0; i < 16; i += 4) {
            float4 v = *(const float4*)(qp + i);
            Qs[ds+i+0][r] = v.x; Qs[ds+i+1][r] = v.y;
            Qs[ds+i+2][r] = v.z; Qs[ds+i+3][r] = v.w;
        }
    }

    float O[4][4];
    float mrow[4], lrow[4];
    #pragma unroll
    for (int i = 0; i < 4; i++) {
        mrow[i] = -1e30f; lrow[i] = 0.f;
        #pragma unroll
        for (int j = 0; j < 4; j++) O[i][j] = 0.f;
    }
    const int q0 = qb*64 + ty*4;   // global q index of this thread's row 0

    for (int j = 0; j <= qb; j++) {
        __syncthreads();   // previous iter done with KPs/Vs
        {
            int r = tid >> 2, ds = (tid & 3) << 4;
            const float* kp = g_k + ((size_t)bh*Tv + j*64 + r)*DHv + ds;
            const float* vp = g_v + ((size_t)bh*Tv + j*64 + r)*DHv + ds;
            #pragma unroll
            for (int i = 0; i < 16; i += 4) {
                float4 kv = *(const float4*)(kp + i);
                KPs[ds+i+0][r] = kv.x; KPs[ds+i+1][r] = kv.y;
                KPs[ds+i+2][r] = kv.z; KPs[ds+i+3][r] = kv.w;
                float4 vv = *(const float4*)(vp + i);
                *(float4*)&Vs[r][ds+i] = vv;
            }
        }
        __syncthreads();

        // --- S = Q K^T (scaled) ---
        float s[4][4];
        #pragma unroll
        for (int i = 0; i < 4; i++)
            #pragma unroll
            for (int jj = 0; jj < 4; jj++) s[i][jj] = 0.f;
        #pragma unroll 8
        for (int d = 0; d < 64; d++) {
            float4 a = *(const float4*)&Qs[d][ty*4];
            float4 b = *(const float4*)&KPs[d][tx*4];
            float av[4] = {a.x, a.y, a.z, a.w};
            float bv4[4] = {b.x, b.y, b.z, b.w};
            #pragma unroll
            for (int i = 0; i < 4; i++)
                #pragma unroll
                for (int jj = 0; jj < 4; jj++)
                    s[i][jj] = fmaf(av[i], bv4[jj], s[i][jj]);
        }
        const int k0 = j*64 + tx*4;
        #pragma unroll
        for (int i = 0; i < 4; i++)
            #pragma unroll
            for (int jj = 0; jj < 4; jj++) {
                s[i][jj] *= 0.125f;                    // DH^-0.5
                if (k0 + jj > q0 + i) s[i][jj] = -1e30f;  // causal
            }
        __syncthreads();   // done reading KPs as K^T

        // --- online softmax (row reductions across the 16 tx lanes) ---
        #pragma unroll
        for (int i = 0; i < 4; i++) {
            float mx = s[i][0];
            #pragma unroll
            for (int jj = 1; jj < 4; jj++) mx = fmaxf(mx, s[i][jj]);
            #pragma unroll
            for (int off = 8; off >= 1; off >>= 1)
                mx = fmaxf(mx, __shfl_xor_sync(0xffffffffu, mx, off, 16));
            float mn   = fmaxf(mrow[i], mx);
            float corr = __expf(mrow[i] - mn);
            float rs = 0.f;
            #pragma unroll
            for (int jj = 0; jj < 4; jj++) {
                s[i][jj] = __expf(s[i][jj] - mn);
                rs += s[i][jj];
            }
            #pragma unroll
            for (int off = 8; off >= 1; off >>= 1)
                rs += __shfl_xor_sync(0xffffffffu, rs, off, 16);
            lrow[i] = lrow[i]*corr + rs;
            mrow[i] = mn;
            #pragma unroll
            for (int jj = 0; jj < 4; jj++) {
                O[i][jj] *= corr;
                if (k0 + jj == q0 + i) s[i][jj] = 0.f;   // exclude diagonal from PV
                KPs[ty*4 + i][tx*4 + jj] = s[i][jj];     // P [q][c]
            }
        }
        __syncthreads();

        // --- O += P V ---
        #pragma unroll 4
        for (int c = 0; c < 64; c += 4) {
            float4 a0 = *(const float4*)&KPs[ty*4+0][c];
            float4 a1 = *(const float4*)&KPs[ty*4+1][c];
            float4 a2 = *(const float4*)&KPs[ty*4+2][c];
            float4 a3 = *(const float4*)&KPs[ty*4+3][c];
            float4 b0 = *(const float4*)&Vs[c+0][tx*4];
            float4 b1 = *(const float4*)&Vs[c+1][tx*4];
            float4 b2 = *(const float4*)&Vs[c+2][tx*4];
            float4 b3 = *(const float4*)&Vs[c+3][tx*4];
            float pa[4][4] = {{a0.x,a0.y,a0.z,a0.w},{a1.x,a1.y,a1.z,a1.w},
                              {a2.x,a2.y,a2.z,a2.w},{a3.x,a3.y,a3.z,a3.w}};
            float vb[4][4] = {{b0.x,b0.y,b0.z,b0.w},{b1.x,b1.y,b1.z,b1.w},
                              {b2.x,b2.y,b2.z,b2.w},{b3.x,b3.y,b3.z,b3.w}};
            #pragma unroll
            for (int i = 0; i < 4; i++)
                #pragma unroll
                for (int jj = 0; jj < 4; jj++) {
                    float o = O[i][jj];
                    o = fmaf(pa[i][0], vb[0][jj], o);
                    o = fmaf(pa[i][1], vb[1][jj], o);
                    o = fmaf(pa[i][2], vb[2][jj], o);
                    o = fmaf(pa[i][3], vb[3][jj], o);
                    O[i][jj] = o;
                }
        }
    }

    // write out: g_attn[b][t][h*64 + dh]
    const int bb = bh >> 4, h = bh & 15;
    #pragma unroll
    for (int i = 0; i < 4; i++) {
        float inv = 1.f / lrow[i];
        size_t base = ((size_t)bb*Tv + qb*64 + ty*4 + i)*Dv + h*64 + tx*4;
        #pragma unroll
        for (int jj = 0; jj < 4; jj++)
            g_attn[base + jj] = O[i][jj] * inv;
    }
}

// ============================================================================
extern "C" void kernel_launch(void* const* d_in, const int* in_sizes, int n_in,
                              void* d_out, int out_size)
{
    const float* x     = (const float*)d_in[0];
    const float* cosT  = (const float*)d_in[1];
    const float* sinT  = (const float*)d_in[2];
    const float* Wqkv  = (const float*)d_in[3];
    const float* Wproj = (const float*)d_in[4];

    float* attn_ptr = nullptr;
    cudaGetSymbolAddress((void**)&attn_ptr, g_attn);

    // 1) QKV projection, scattered into [b,h,t,dh] layout
    gemm_tn<0><<<dim3(NQKV/128, MROWS/128), 256>>>(x, Wqkv, nullptr);
    // 2) RoPE on q,k
    rope_kernel<<<(Bv*Hv*Tv*HALFv + 255)/256, 256>>>(cosT, sinT);
    // 3) causal attention with diagonal-excluded PV
    attn_kernel<<<dim3(Tv/64, Bv*Hv), 256>>>();
    // 4) output projection -> d_out
    gemm_tn<1><<<dim3(Dv/128, MROWS/128), 256>>>(attn_ptr, Wproj, (float*)d_out);
}

// round 4
// speedup vs baseline: 1.4839x; 1.4839x over previous
#include <cuda_runtime.h>
#include <math.h>
#include <stdint.h>

#define Bv    4
#define Tv    2048
#define Dv    1024
#define Hv    16
#define DHv   64
#define HALFv 32
#define MROWS (Bv*Tv)      // 8192
#define NQKV  (3*Dv)       // 3072

// ---- scratch (device globals) ----
__device__ float g_q[Bv*Hv*Tv*DHv];     // [b,h,t,dh]
__device__ float g_k[Bv*Hv*Tv*DHv];
__device__ float g_v[Bv*Hv*Tv*DHv];
__device__ float g_attn[MROWS*Dv];      // [b,t,d]

__device__ __forceinline__ uint32_t f2tf32(float f) {
    uint32_t u;
    asm("cvt.rna.tf32.f32 %0, %1;" : "=r"(u) : "f"(f));
    return u;
}

__device__ __forceinline__ void mma_tf32(
    float& c0, float& c1, float& c2, float& c3,
    uint32_t a0, uint32_t a1, uint32_t a2, uint32_t a3,
    uint32_t b0, uint32_t b1)
{
    asm volatile(
        "mma.sync.aligned.m16n8k8.row.col.f32.tf32.tf32.f32 "
        "{%0,%1,%2,%3}, {%4,%5,%6,%7}, {%8,%9}, {%0,%1,%2,%3};"
        : "+f"(c0), "+f"(c1), "+f"(c2), "+f"(c3)
        : "r"(a0), "r"(a1), "r"(a2), "r"(a3), "r"(b0), "r"(b1));
}

// ============================================================================
// tf32 mma.sync GEMM: C[M,N] = A[M,K] * Bw[N,K]^T, K = 1024.
// CTA tile 128x128, 8 warps (2x4), warp tile 64x32, K-chunk 16, double buffer.
// smem layout [k][m] / [k][n], pitch 136 (stride%32==8 -> conflict-free frags).
// MODE 0: scatter into g_q/g_k/g_v ([b,h,t,dh]). MODE 1: row-major C.
// ============================================================================
#define PITCH 136
#define NCHUNK (Dv / 16)    // 64

template<int MODE>
__global__ __launch_bounds__(256, 2)
void gemm_mma(const float* __restrict__ A, const float* __restrict__ Bw,
              float* __restrict__ C)
{
    __shared__ uint32_t As[2][16][PITCH];
    __shared__ uint32_t Bs[2][16][PITCH];

    const int tid  = threadIdx.x;
    const int wid  = tid >> 5, lane = tid & 31;
    const int gid  = lane >> 2, tg = lane & 3;      // group id / thread-in-group
    const int wm   = (wid >> 2) * 64;               // warp row offset (0,64)
    const int wn   = (wid & 3) * 32;                // warp col offset (0..96)
    const int m0   = blockIdx.y * 128, n0 = blockIdx.x * 128;

    // global load assignment: row r = tid&127, k-half kh = tid>>7
    const int lr = tid & 127, kh = (tid >> 7) * 8;
    const float* gA = A  + (size_t)(m0 + lr) * Dv + kh;
    const float* gB = Bw + (size_t)(n0 + lr) * Dv + kh;

    float acc[4][4][4];
    #pragma unroll
    for (int i = 0; i < 4; i++)
        #pragma unroll
        for (int j = 0; j < 4; j++)
            #pragma unroll
            for (int r = 0; r < 4; r++) acc[i][j][r] = 0.f;

    // prime buffer 0
    {
        float4 a0 = *(const float4*)(gA + 0);
        float4 a1 = *(const float4*)(gA + 4);
        float4 b0 = *(const float4*)(gB + 0);
        float4 b1 = *(const float4*)(gB + 4);
        const float av[8] = {a0.x,a0.y,a0.z,a0.w,a1.x,a1.y,a1.z,a1.w};
        const float bv[8] = {b0.x,b0.y,b0.z,b0.w,b1.x,b1.y,b1.z,b1.w};
        #pragma unroll
        for (int j = 0; j < 8; j++) {
            As[0][kh + j][lr] = f2tf32(av[j]);
            Bs[0][kh + j][lr] = f2tf32(bv[j]);
        }
    }
    __syncthreads();

    for (int ch = 0; ch < NCHUNK; ++ch) {
        const int cur = ch & 1;
        float av[8], bv[8];
        if (ch + 1 < NCHUNK) {
            const float* pa = gA + (ch + 1) * 16;
            const float* pb = gB + (ch + 1) * 16;
            float4 t0 = *(const float4*)(pa + 0);
            float4 t1 = *(const float4*)(pa + 4);
            float4 t2 = *(const float4*)(pb + 0);
            float4 t3 = *(const float4*)(pb + 4);
            av[0]=t0.x;av[1]=t0.y;av[2]=t0.z;av[3]=t0.w;
            av[4]=t1.x;av[5]=t1.y;av[6]=t1.z;av[7]=t1.w;
            bv[0]=t2.x;bv[1]=t2.y;bv[2]=t2.z;bv[3]=t2.w;
            bv[4]=t3.x;bv[5]=t3.y;bv[6]=t3.z;bv[7]=t3.w;
        }

        // compute 2 x k8 steps from smem[cur]
        #pragma unroll
        for (int ks = 0; ks < 2; ks++) {
            const int k0 = ks * 8;
            uint32_t af[4][4], bf[4][2];
            #pragma unroll
            for (int mi = 0; mi < 4; mi++) {
                const int mb = wm + mi * 16 + gid;
                af[mi][0] = As[cur][k0 + tg    ][mb];
                af[mi][1] = As[cur][k0 + tg    ][mb + 8];
                af[mi][2] = As[cur][k0 + tg + 4][mb];
                af[mi][3] = As[cur][k0 + tg + 4][mb + 8];
            }
            #pragma unroll
            for (int ni = 0; ni < 4; ni++) {
                const int nb = wn + ni * 8 + gid;
                bf[ni][0] = Bs[cur][k0 + tg    ][nb];
                bf[ni][1] = Bs[cur][k0 + tg + 4][nb];
            }
            #pragma unroll
            for (int mi = 0; mi < 4; mi++)
                #pragma unroll
                for (int ni = 0; ni < 4; ni++)
                    mma_tf32(acc[mi][ni][0], acc[mi][ni][1],
                             acc[mi][ni][2], acc[mi][ni][3],
                             af[mi][0], af[mi][1], af[mi][2], af[mi][3],
                             bf[ni][0], bf[ni][1]);
        }

        if (ch + 1 < NCHUNK) {
            const int nxt = cur ^ 1;
            #pragma unroll
            for (int j = 0; j < 8; j++) {
                As[nxt][kh + j][lr] = f2tf32(av[j]);
                Bs[nxt][kh + j][lr] = f2tf32(bv[j]);
            }
        }
        __syncthreads();
    }

    // ---- epilogue ----
    #pragma unroll
    for (int mi = 0; mi < 4; mi++) {
        #pragma unroll
        for (int half = 0; half < 2; half++) {      // c0c1 rows gid, c2c3 rows gid+8
            const int m = m0 + wm + mi * 16 + gid + half * 8;
            const int bb = m >> 11, trow = m & (Tv - 1);
            #pragma unroll
            for (int ni = 0; ni < 4; ni++) {
                const int n = n0 + wn + ni * 8 + tg * 2;
                float2 val;
                val.x = acc[mi][ni][half * 2 + 0];
                val.y = acc[mi][ni][half * 2 + 1];
                if (MODE == 0) {
                    const int wh = n >> 10;
                    const int d  = n & (Dv - 1);
                    const int h  = d >> 6, dd = d & 63;
                    float* dst = ((wh == 0) ? g_q : (wh == 1) ? g_k : g_v)
                               + ((size_t)(bb * Hv + h) * Tv + trow) * DHv + dd;
                    *(float2*)dst = val;
                } else {
                    *(float2*)(C + (size_t)m * Dv + n) = val;
                }
            }
        }
    }
}

// ============================================================================
// RoPE on g_q and g_k in place.
// ============================================================================
__global__ void rope_kernel(const float* __restrict__ cosT,
                            const float* __restrict__ sinT)
{
    int gid = blockIdx.x * blockDim.x + threadIdx.x;
    if (gid >= Bv*Hv*Tv*HALFv) return;
    int i   = gid & (HALFv - 1);
    int row = gid >> 5;              // bh*T + t
    int t   = row & (Tv - 1);
    float c = cosT[t*HALFv + i];
    float s = sinT[t*HALFv + i];

    float* qp = g_q + (size_t)row * DHv;
    float q1 = qp[i], q2 = qp[i + HALFv];
    qp[i]          = q1*c - q2*s;
    qp[i + HALFv]  = q1*s + q2*c;

    float* kp = g_k + (size_t)row * DHv;
    float k1 = kp[i], k2 = kp[i + HALFv];
    kp[i]          = k1*c - k2*s;
    kp[i + HALFv]  = k1*s + k2*c;
}

// ============================================================================
// Flash attention (FFMA), causal, diagonal excluded from PV numerator.
// ============================================================================
__global__ __launch_bounds__(256)
void attn_kernel()
{
    __shared__ float Qs[64][64];   // [d][q]
    __shared__ float KPs[64][64];  // K^T [d][c], then P [q][c]
    __shared__ float Vs[64][64];   // [c][dh]

    const int qb = blockIdx.x;
    const int bh = blockIdx.y;
    const int tid = threadIdx.x;
    const int tx = tid & 15, ty = tid >> 4;

    {
        int r = tid >> 2, ds = (tid & 3) << 4;
        const float* qp = g_q + ((size_t)bh*Tv + qb*64 + r)*DHv + ds;
        #pragma unroll
        for (int i = 0; i < 16; i += 4) {
            float4 v = *(const float4*)(qp + i);
            Qs[ds+i+0][r] = v.x; Qs[ds+i+1][r] = v.y;
            Qs[ds+i+2][r] = v.z; Qs[ds+i+3][r] = v.w;
        }
    }

    float O[4][4];
    float mrow[4], lrow[4];
    #pragma unroll
    for (int i = 0; i < 4; i++) {
        mrow[i] = -1e30f; lrow[i] = 0.f;
        #pragma unroll
        for (int j = 0; j < 4; j++) O[i][j] = 0.f;
    }
    const int q0 = qb*64 + ty*4;

    for (int j = 0; j <= qb; j++) {
        __syncthreads();
        {
            int r = tid >> 2, ds = (tid & 3) << 4;
            const float* kp = g_k + ((size_t)bh*Tv + j*64 + r)*DHv + ds;
            const float* vp = g_v + ((size_t)bh*Tv + j*64 + r)*DHv + ds;
            #pragma unroll
            for (int i = 0; i < 16; i += 4) {
                float4 kv = *(const float4*)(kp + i);
                KPs[ds+i+0][r] = kv.x; KPs[ds+i+1][r] = kv.y;
                KPs[ds+i+2][r] = kv.z; KPs[ds+i+3][r] = kv.w;
                float4 vv = *(const float4*)(vp + i);
                *(float4*)&Vs[r][ds+i] = vv;
            }
        }
        __syncthreads();

        float s[4][4];
        #pragma unroll
        for (int i = 0; i < 4; i++)
            #pragma unroll
            for (int jj = 0; jj < 4; jj++) s[i][jj] = 0.f;
        #pragma unroll 8
        for (int d = 0; d < 64; d++) {
            float4 a = *(const float4*)&Qs[d][ty*4];
            float4 b = *(const float4*)&KPs[d][tx*4];
            float av[4] = {a.x, a.y, a.z, a.w};
            float bv4[4] = {b.x, b.y, b.z, b.w};
            #pragma unroll
            for (int i = 0; i < 4; i++)
                #pragma unroll
                for (int jj = 0; jj < 4; jj++)
                    s[i][jj] = fmaf(av[i], bv4[jj], s[i][jj]);
        }
        const int k0 = j*64 + tx*4;
        #pragma unroll
        for (int i = 0; i < 4; i++)
            #pragma unroll
            for (int jj = 0; jj < 4; jj++) {
                s[i][jj] *= 0.125f;
                if (k0 + jj > q0 + i) s[i][jj] = -1e30f;
            }
        __syncthreads();

        #pragma unroll
        for (int i = 0; i < 4; i++) {
            float mx = s[i][0];
            #pragma unroll
            for (int jj = 1; jj < 4; jj++) mx = fmaxf(mx, s[i][jj]);
            #pragma unroll
            for (int off = 8; off >= 1; off >>= 1)
                mx = fmaxf(mx, __shfl_xor_sync(0xffffffffu, mx, off, 16));
            float mn   = fmaxf(mrow[i], mx);
            float corr = __expf(mrow[i] - mn);
            float rs = 0.f;
            #pragma unroll
            for (int jj = 0; jj < 4; jj++) {
                s[i][jj] = __expf(s[i][jj] - mn);
                rs += s[i][jj];
            }
            #pragma unroll
            for (int off = 8; off >= 1; off >>= 1)
                rs += __shfl_xor_sync(0xffffffffu, rs, off, 16);
            lrow[i] = lrow[i]*corr + rs;
            mrow[i] = mn;
            #pragma unroll
            for (int jj = 0; jj < 4; jj++) {
                O[i][jj] *= corr;
                if (k0 + jj == q0 + i) s[i][jj] = 0.f;
                KPs[ty*4 + i][tx*4 + jj] = s[i][jj];
            }
        }
        __syncthreads();

        #pragma unroll 4
        for (int c = 0; c < 64; c += 4) {
            float4 a0 = *(const float4*)&KPs[ty*4+0][c];
            float4 a1 = *(const float4*)&KPs[ty*4+1][c];
            float4 a2 = *(const float4*)&KPs[ty*4+2][c];
            float4 a3 = *(const float4*)&KPs[ty*4+3][c];
            float4 b0 = *(const float4*)&Vs[c+0][tx*4];
            float4 b1 = *(const float4*)&Vs[c+1][tx*4];
            float4 b2 = *(const float4*)&Vs[c+2][tx*4];
            float4 b3 = *(const float4*)&Vs[c+3][tx*4];
            float pa[4][4] = {{a0.x,a0.y,a0.z,a0.w},{a1.x,a1.y,a1.z,a1.w},
                              {a2.x,a2.y,a2.z,a2.w},{a3.x,a3.y,a3.z,a3.w}};
            float vb[4][4] = {{b0.x,b0.y,b0.z,b0.w},{b1.x,b1.y,b1.z,b1.w},
                              {b2.x,b2.y,b2.z,b2.w},{b3.x,b3.y,b3.z,b3.w}};
            #pragma unroll
            for (int i = 0; i < 4; i++)
                #pragma unroll
                for (int jj = 0; jj < 4; jj++) {
                    float o = O[i][jj];
                    o = fmaf(pa[i][0], vb[0][jj], o);
                    o = fmaf(pa[i][1], vb[1][jj], o);
                    o = fmaf(pa[i][2], vb[2][jj], o);
                    o = fmaf(pa[i][3], vb[3][jj], o);
                    O[i][jj] = o;
                }
        }
    }

    const int bb = bh >> 4, h = bh & 15;
    #pragma unroll
    for (int i = 0; i < 4; i++) {
        float inv = 1.f / lrow[i];
        size_t base = ((size_t)bb*Tv + qb*64 + ty*4 + i)*Dv + h*64 + tx*4;
        #pragma unroll
        for (int jj = 0; jj < 4; jj++)
            g_attn[base + jj] = O[i][jj] * inv;
    }
}

// ============================================================================
extern "C" void kernel_launch(void* const* d_in, const int* in_sizes, int n_in,
                              void* d_out, int out_size)
{
    const float* x     = (const float*)d_in[0];
    const float* cosT  = (const float*)d_in[1];
    const float* sinT  = (const float*)d_in[2];
    const float* Wqkv  = (const float*)d_in[3];
    const float* Wproj = (const float*)d_in[4];

    float* attn_ptr = nullptr;
    cudaGetSymbolAddress((void**)&attn_ptr, g_attn);

    // 1) QKV projection (tf32 mma.sync), scattered into [b,h,t,dh]
    gemm_mma<0><<<dim3(NQKV/128, MROWS/128), 256>>>(x, Wqkv, nullptr);
    // 2) RoPE on q,k
    rope_kernel<<<(Bv*Hv*Tv*HALFv + 255)/256, 256>>>(cosT, sinT);
    // 3) causal attention with diagonal-excluded PV
    attn_kernel<<<dim3(Tv/64, Bv*Hv), 256>>>();
    // 4) output projection (tf32 mma.sync) -> d_out
    gemm_mma<1><<<dim3(Dv/128, MROWS/128), 256>>>(attn_ptr, Wproj, (float*)d_out);
}

// round 5
// speedup vs baseline: 2.0196x; 1.3610x over previous
#include <cuda_runtime.h>
#include <math.h>
#include <stdint.h>

#define Bv    4
#define Tv    2048
#define Dv    1024
#define Hv    16
#define DHv   64
#define HALFv 32
#define MROWS (Bv*Tv)      // 8192
#define NQKV  (3*Dv)       // 3072

// ---- scratch (device globals) ----
__device__ float g_q[Bv*Hv*Tv*DHv];     // [b,h,t,dh]
__device__ float g_k[Bv*Hv*Tv*DHv];
__device__ float g_v[Bv*Hv*Tv*DHv];
__device__ float g_attn[MROWS*Dv];      // [b,t,d]

__device__ __forceinline__ uint32_t f2tf32(float f) {
    uint32_t u;
    asm("cvt.rna.tf32.f32 %0, %1;" : "=r"(u) : "f"(f));
    return u;
}

__device__ __forceinline__ void mma_tf32(
    float* c, uint32_t a0, uint32_t a1, uint32_t a2, uint32_t a3,
    uint32_t b0, uint32_t b1)
{
    asm volatile(
        "mma.sync.aligned.m16n8k8.row.col.f32.tf32.tf32.f32 "
        "{%0,%1,%2,%3}, {%4,%5,%6,%7}, {%8,%9}, {%0,%1,%2,%3};"
        : "+f"(c[0]), "+f"(c[1]), "+f"(c[2]), "+f"(c[3])
        : "r"(a0), "r"(a1), "r"(a2), "r"(a3), "r"(b0), "r"(b1));
}

// ============================================================================
// tf32 mma.sync dense GEMM (unchanged from R4): C[M,N] = A[M,K]*Bw[N,K]^T
// ============================================================================
#define PITCH 136
#define NCHUNK (Dv / 16)    // 64

template<int MODE>
__global__ __launch_bounds__(256, 2)
void gemm_mma(const float* __restrict__ A, const float* __restrict__ Bw,
              float* __restrict__ C)
{
    __shared__ uint32_t As[2][16][PITCH];
    __shared__ uint32_t Bs[2][16][PITCH];

    const int tid  = threadIdx.x;
    const int wid  = tid >> 5, lane = tid & 31;
    const int gid  = lane >> 2, tg = lane & 3;
    const int wm   = (wid >> 2) * 64;
    const int wn   = (wid & 3) * 32;
    const int m0   = blockIdx.y * 128, n0 = blockIdx.x * 128;

    const int lr = tid & 127, kh = (tid >> 7) * 8;
    const float* gA = A  + (size_t)(m0 + lr) * Dv + kh;
    const float* gB = Bw + (size_t)(n0 + lr) * Dv + kh;

    float acc[4][4][4];
    #pragma unroll
    for (int i = 0; i < 4; i++)
        #pragma unroll
        for (int j = 0; j < 4; j++)
            #pragma unroll
            for (int r = 0; r < 4; r++) acc[i][j][r] = 0.f;

    {
        float4 a0 = *(const float4*)(gA + 0);
        float4 a1 = *(const float4*)(gA + 4);
        float4 b0 = *(const float4*)(gB + 0);
        float4 b1 = *(const float4*)(gB + 4);
        const float av[8] = {a0.x,a0.y,a0.z,a0.w,a1.x,a1.y,a1.z,a1.w};
        const float bv[8] = {b0.x,b0.y,b0.z,b0.w,b1.x,b1.y,b1.z,b1.w};
        #pragma unroll
        for (int j = 0; j < 8; j++) {
            As[0][kh + j][lr] = f2tf32(av[j]);
            Bs[0][kh + j][lr] = f2tf32(bv[j]);
        }
    }
    __syncthreads();

    for (int ch = 0; ch < NCHUNK; ++ch) {
        const int cur = ch & 1;
        float av[8], bv[8];
        if (ch + 1 < NCHUNK) {
            const float* pa = gA + (ch + 1) * 16;
            const float* pb = gB + (ch + 1) * 16;
            float4 t0 = *(const float4*)(pa + 0);
            float4 t1 = *(const float4*)(pa + 4);
            float4 t2 = *(const float4*)(pb + 0);
            float4 t3 = *(const float4*)(pb + 4);
            av[0]=t0.x;av[1]=t0.y;av[2]=t0.z;av[3]=t0.w;
            av[4]=t1.x;av[5]=t1.y;av[6]=t1.z;av[7]=t1.w;
            bv[0]=t2.x;bv[1]=t2.y;bv[2]=t2.z;bv[3]=t2.w;
            bv[4]=t3.x;bv[5]=t3.y;bv[6]=t3.z;bv[7]=t3.w;
        }

        #pragma unroll
        for (int ks = 0; ks < 2; ks++) {
            const int k0 = ks * 8;
            uint32_t af[4][4], bf[4][2];
            #pragma unroll
            for (int mi = 0; mi < 4; mi++) {
                const int mb = wm + mi * 16 + gid;
                af[mi][0] = As[cur][k0 + tg    ][mb];
                af[mi][1] = As[cur][k0 + tg    ][mb + 8];
                af[mi][2] = As[cur][k0 + tg + 4][mb];
                af[mi][3] = As[cur][k0 + tg + 4][mb + 8];
            }
            #pragma unroll
            for (int ni = 0; ni < 4; ni++) {
                const int nb = wn + ni * 8 + gid;
                bf[ni][0] = Bs[cur][k0 + tg    ][nb];
                bf[ni][1] = Bs[cur][k0 + tg + 4][nb];
            }
            #pragma unroll
            for (int mi = 0; mi < 4; mi++)
                #pragma unroll
                for (int ni = 0; ni < 4; ni++)
                    mma_tf32(acc[mi][ni],
                             af[mi][0], af[mi][1], af[mi][2], af[mi][3],
                             bf[ni][0], bf[ni][1]);
        }

        if (ch + 1 < NCHUNK) {
            const int nxt = cur ^ 1;
            #pragma unroll
            for (int j = 0; j < 8; j++) {
                As[nxt][kh + j][lr] = f2tf32(av[j]);
                Bs[nxt][kh + j][lr] = f2tf32(bv[j]);
            }
        }
        __syncthreads();
    }

    #pragma unroll
    for (int mi = 0; mi < 4; mi++) {
        #pragma unroll
        for (int half = 0; half < 2; half++) {
            const int m = m0 + wm + mi * 16 + gid + half * 8;
            const int bb = m >> 11, trow = m & (Tv - 1);
            #pragma unroll
            for (int ni = 0; ni < 4; ni++) {
                const int n = n0 + wn + ni * 8 + tg * 2;
                float2 val;
                val.x = acc[mi][ni][half * 2 + 0];
                val.y = acc[mi][ni][half * 2 + 1];
                if (MODE == 0) {
                    const int wh = n >> 10;
                    const int d  = n & (Dv - 1);
                    const int h  = d >> 6, dd = d & 63;
                    float* dst = ((wh == 0) ? g_q : (wh == 1) ? g_k : g_v)
                               + ((size_t)(bb * Hv + h) * Tv + trow) * DHv + dd;
                    *(float2*)dst = val;
                } else {
                    *(float2*)(C + (size_t)m * Dv + n) = val;
                }
            }
        }
    }
}

// ============================================================================
// RoPE on g_q and g_k in place.
// ============================================================================
__global__ void rope_kernel(const float* __restrict__ cosT,
                            const float* __restrict__ sinT)
{
    int gid = blockIdx.x * blockDim.x + threadIdx.x;
    if (gid >= Bv*Hv*Tv*HALFv) return;
    int i   = gid & (HALFv - 1);
    int row = gid >> 5;
    int t   = row & (Tv - 1);
    float c = cosT[t*HALFv + i];
    float s = sinT[t*HALFv + i];

    float* qp = g_q + (size_t)row * DHv;
    float q1 = qp[i], q2 = qp[i + HALFv];
    qp[i]          = q1*c - q2*s;
    qp[i + HALFv]  = q1*s + q2*c;

    float* kp = g_k + (size_t)row * DHv;
    float k1 = kp[i], k2 = kp[i + HALFv];
    kp[i]          = k1*c - k2*s;
    kp[i + HALFv]  = k1*s + k2*c;
}

// ============================================================================
// Flash attention on tensor cores.
// q-tile 128 (8 warps x 16 rows), key-tile 64 per iter.
// QK^T: 3xtf32 (hi/lo split, ~fp32 accurate). PV: single tf32.
// Diagonal kept in softmax denominator, zeroed in P numerator.
// Smem (dynamic, 115200 B):
//   Qlop [8w][8ks][32]  uint4   @0      (32768)  Q-lo a-frags
//   Khi  [8ks][8nf][32] uint2   @32768  (16384)  K-hi b-frags
//   Klo                         @49152  (16384)
//   Vpk  [8cs][8df][33] uint2   @65536  (16896)  V b-frags (padded)
//   Ppk  [8w][8cs][32]  float4  @82432  (32768)  P a-frags
//   Qraw [128][68] float        @32768  (34816)  staging, pre-loop only
// ============================================================================
#define ATTN_SMEM 115200

__global__ __launch_bounds__(256, 1)
void attn_mma()
{
    extern __shared__ char sm[];
    uint4*  Qlop = (uint4*)sm;
    uint2*  Khi  = (uint2*)(sm + 32768);
    uint2*  Klo  = (uint2*)(sm + 49152);
    uint2*  Vpk  = (uint2*)(sm + 65536);
    float4* Ppk  = (float4*)(sm + 82432);
    float*  Qraw = (float*)(sm + 32768);

    const int qb = (int)gridDim.x - 1 - (int)blockIdx.x;  // big tiles first
    const int bh = blockIdx.y;
    const int tid = threadIdx.x;
    const int w = tid >> 5, lane = tid & 31;
    const int gid = lane >> 2, tg = lane & 3;

    // ---- stage Q tile [128][64] into Qraw (pitch 68) ----
    {
        const float* qg = g_q + ((size_t)bh * Tv + qb * 128) * DHv;
        #pragma unroll
        for (int i = 0; i < 8; i++) {
            int f = tid + i * 256;           // float4 idx
            int r = f >> 4, c4 = f & 15;
            *(float4*)(Qraw + r * 68 + c4 * 4) = *(const float4*)(qg + r * 64 + c4 * 4);
        }
    }
    __syncthreads();

    // ---- extract Q fragments: hi in regs, lo packed to smem ----
    uint32_t Qh[8][4];
    {
        #pragma unroll
        for (int ks = 0; ks < 8; ks++) {
            float q0 = Qraw[(16*w + gid    ) * 68 + ks*8 + tg    ] * 0.125f;
            float q1 = Qraw[(16*w + gid + 8) * 68 + ks*8 + tg    ] * 0.125f;
            float q2 = Qraw[(16*w + gid    ) * 68 + ks*8 + tg + 4] * 0.125f;
            float q3 = Qraw[(16*w + gid + 8) * 68 + ks*8 + tg + 4] * 0.125f;
            uint32_t h0 = f2tf32(q0), h1 = f2tf32(q1), h2 = f2tf32(q2), h3 = f2tf32(q3);
            Qh[ks][0] = h0; Qh[ks][1] = h1; Qh[ks][2] = h2; Qh[ks][3] = h3;
            uint4 lo;
            lo.x = f2tf32(q0 - __uint_as_float(h0));
            lo.y = f2tf32(q1 - __uint_as_float(h1));
            lo.z = f2tf32(q2 - __uint_as_float(h2));
            lo.w = f2tf32(q3 - __uint_as_float(h3));
            Qlop[(w*8 + ks)*32 + lane] = lo;
        }
    }

    const int rowA = qb*128 + 16*w + gid;
    const int rowB = rowA + 8;

    float O[8][4];
    #pragma unroll
    for (int d = 0; d < 8; d++)
        #pragma unroll
        for (int r = 0; r < 4; r++) O[d][r] = 0.f;
    float m0 = -1e30f, m1 = -1e30f, l0 = 0.f, l1 = 0.f;

    const int niter = 2 * (qb + 1);
    for (int j = 0; j < niter; j++) {
        const int k0g = j * 64;
        __syncthreads();   // previous consumers of Khi/Klo/Vpk done (also covers Qraw pre-loop)

        // ---- load K tile -> hi/lo b-frag packs ----
        {
            const int n = tid >> 2, p = tid & 3;
            const float* kp = g_k + ((size_t)bh*Tv + k0g + n) * 64 + p * 16;
            float4 f0 = *(const float4*)(kp + 0);
            float4 f1 = *(const float4*)(kp + 4);
            float4 f2 = *(const float4*)(kp + 8);
            float4 f3 = *(const float4*)(kp + 12);
            float xs[16] = {f0.x,f0.y,f0.z,f0.w, f1.x,f1.y,f1.z,f1.w,
                            f2.x,f2.y,f2.z,f2.w, f3.x,f3.y,f3.z,f3.w};
            #pragma unroll
            for (int jj = 0; jj < 2; jj++) {
                const int ks = 2*p + jj;
                #pragma unroll
                for (int tgi = 0; tgi < 4; tgi++) {
                    float x1 = xs[jj*8 + tgi], x2 = xs[jj*8 + 4 + tgi];
                    uint32_t h1 = f2tf32(x1), h2 = f2tf32(x2);
                    int idx = (ks*8 + (n >> 3))*32 + (n & 7)*4 + tgi;
                    Khi[idx] = make_uint2(h1, h2);
                    Klo[idx] = make_uint2(f2tf32(x1 - __uint_as_float(h1)),
                                          f2tf32(x2 - __uint_as_float(h2)));
                }
            }
        }
        // ---- load V tile -> b-frag pack ----
        {
            const int p = tid & 7, pi = tid >> 3;
            const int cs = pi >> 2, tgv = pi & 3;
            const int c = cs*8 + tgv;
            const float* vp0 = g_v + ((size_t)bh*Tv + k0g + c) * 64 + p * 8;
            const float* vp1 = vp0 + 4 * 64;
            float4 a0 = *(const float4*)(vp0 + 0);
            float4 a1 = *(const float4*)(vp0 + 4);
            float4 b0 = *(const float4*)(vp1 + 0);
            float4 b1 = *(const float4*)(vp1 + 4);
            float va[8] = {a0.x,a0.y,a0.z,a0.w, a1.x,a1.y,a1.z,a1.w};
            float vb[8] = {b0.x,b0.y,b0.z,b0.w, b1.x,b1.y,b1.z,b1.w};
            #pragma unroll
            for (int k = 0; k < 8; k++)
                Vpk[(cs*8 + p)*33 + 4*k + tgv] =
                    make_uint2(f2tf32(va[k]), f2tf32(vb[k]));
        }
        __syncthreads();

        // ---- S = Q K^T (3xtf32) ----
        float S[8][4];
        #pragma unroll
        for (int nf = 0; nf < 8; nf++)
            #pragma unroll
            for (int r = 0; r < 4; r++) S[nf][r] = 0.f;
        #pragma unroll
        for (int ks = 0; ks < 8; ks++) {
            uint4 ql = Qlop[(w*8 + ks)*32 + lane];
            #pragma unroll
            for (int nf = 0; nf < 8; nf++) {
                uint2 kh = Khi[(ks*8 + nf)*32 + lane];
                uint2 kl = Klo[(ks*8 + nf)*32 + lane];
                mma_tf32(S[nf], Qh[ks][0], Qh[ks][1], Qh[ks][2], Qh[ks][3], kh.x, kh.y);
                mma_tf32(S[nf], Qh[ks][0], Qh[ks][1], Qh[ks][2], Qh[ks][3], kl.x, kl.y);
                mma_tf32(S[nf], ql.x, ql.y, ql.z, ql.w, kh.x, kh.y);
            }
        }

        // ---- mask + online softmax ----
        float mxA = -1e30f, mxB = -1e30f;
        #pragma unroll
        for (int nf = 0; nf < 8; nf++) {
            const int cA = k0g + nf*8 + 2*tg, cB = cA + 1;
            if (cA > rowA) S[nf][0] = -1e30f;
            if (cB > rowA) S[nf][1] = -1e30f;
            if (cA > rowB) S[nf][2] = -1e30f;
            if (cB > rowB) S[nf][3] = -1e30f;
            mxA = fmaxf(mxA, fmaxf(S[nf][0], S[nf][1]));
            mxB = fmaxf(mxB, fmaxf(S[nf][2], S[nf][3]));
        }
        mxA = fmaxf(mxA, __shfl_xor_sync(0xffffffffu, mxA, 1));
        mxA = fmaxf(mxA, __shfl_xor_sync(0xffffffffu, mxA, 2));
        mxB = fmaxf(mxB, __shfl_xor_sync(0xffffffffu, mxB, 1));
        mxB = fmaxf(mxB, __shfl_xor_sync(0xffffffffu, mxB, 2));
        const float mnA = fmaxf(m0, mxA), mnB = fmaxf(m1, mxB);
        const float corrA = __expf(m0 - mnA), corrB = __expf(m1 - mnB);

        float sA = 0.f, sB = 0.f;
        #pragma unroll
        for (int nf = 0; nf < 8; nf++) {
            const int cA = k0g + nf*8 + 2*tg, cB = cA + 1;
            float e0 = __expf(S[nf][0] - mnA);
            float e1 = __expf(S[nf][1] - mnA);
            float e2 = __expf(S[nf][2] - mnB);
            float e3 = __expf(S[nf][3] - mnB);
            sA += e0 + e1; sB += e2 + e3;
            if (cA == rowA) e0 = 0.f;
            if (cB == rowA) e1 = 0.f;
            if (cA == rowB) e2 = 0.f;
            if (cB == rowB) e3 = 0.f;
            // pack P: column class c' = 2tg (+1)
            {
                const int c0p = 2*tg;
                char* b = (char*)&Ppk[(w*8 + nf)*32 + 4*gid + (c0p & 3)];
                *(uint2*)(b + ((c0p < 4) ? 0 : 8)) = make_uint2(f2tf32(e0), f2tf32(e2));
            }
            {
                const int c1p = 2*tg + 1;
                char* b = (char*)&Ppk[(w*8 + nf)*32 + 4*gid + (c1p & 3)];
                *(uint2*)(b + ((c1p < 4) ? 0 : 8)) = make_uint2(f2tf32(e1), f2tf32(e3));
            }
        }
        sA += __shfl_xor_sync(0xffffffffu, sA, 1);
        sA += __shfl_xor_sync(0xffffffffu, sA, 2);
        sB += __shfl_xor_sync(0xffffffffu, sB, 1);
        sB += __shfl_xor_sync(0xffffffffu, sB, 2);
        l0 = l0 * corrA + sA;  m0 = mnA;
        l1 = l1 * corrB + sB;  m1 = mnB;
        #pragma unroll
        for (int d = 0; d < 8; d++) {
            O[d][0] *= corrA; O[d][1] *= corrA;
            O[d][2] *= corrB; O[d][3] *= corrB;
        }
        __syncwarp();

        // ---- O += P V (single tf32) ----
        #pragma unroll
        for (int cs = 0; cs < 8; cs++) {
            uint4 a = *(const uint4*)&Ppk[(w*8 + cs)*32 + lane];
            #pragma unroll
            for (int df = 0; df < 8; df++) {
                uint2 b = Vpk[(cs*8 + df)*33 + lane];
                mma_tf32(O[df], a.x, a.y, a.z, a.w, b.x, b.y);
            }
        }
        __syncwarp();
    }

    // ---- epilogue ----
    const int bb = bh >> 4, h = bh & 15;
    const float inv0 = 1.f / l0, inv1 = 1.f / l1;
    #pragma unroll
    for (int df = 0; df < 8; df++) {
        const int col = h*64 + df*8 + 2*tg;
        float2 vA = make_float2(O[df][0] * inv0, O[df][1] * inv0);
        float2 vB = make_float2(O[df][2] * inv1, O[df][3] * inv1);
        *(float2*)&g_attn[((size_t)bb*Tv + rowA) * Dv + col] = vA;
        *(float2*)&g_attn[((size_t)bb*Tv + rowB) * Dv + col] = vB;
    }
}

// ============================================================================
extern "C" void kernel_launch(void* const* d_in, const int* in_sizes, int n_in,
                              void* d_out, int out_size)
{
    const float* x     = (const float*)d_in[0];
    const float* cosT  = (const float*)d_in[1];
    const float* sinT  = (const float*)d_in[2];
    const float* Wqkv  = (const float*)d_in[3];
    const float* Wproj = (const float*)d_in[4];

    float* attn_ptr = nullptr;
    cudaGetSymbolAddress((void**)&attn_ptr, g_attn);

    cudaFuncSetAttribute(attn_mma, cudaFuncAttributeMaxDynamicSharedMemorySize, ATTN_SMEM);

    // 1) QKV projection (tf32 mma.sync), scattered into [b,h,t,dh]
    gemm_mma<0><<<dim3(NQKV/128, MROWS/128), 256>>>(x, Wqkv, nullptr);
    // 2) RoPE on q,k
    rope_kernel<<<(Bv*Hv*Tv*HALFv + 255)/256, 256>>>(cosT, sinT);
    // 3) causal attention on tensor cores
    attn_mma<<<dim3(Tv/128, Bv*Hv), 256, ATTN_SMEM>>>();
    // 4) output projection (tf32 mma.sync) -> d_out
    gemm_mma<1><<<dim3(Dv/128, MROWS/128), 256>>>(attn_ptr, Wproj, (float*)d_out);
}